// round 13
// baseline (speedup 1.0000x reference)
#include <cuda_runtime.h>
#include <cuda_bf16.h>
#include <cuda_fp16.h>
#include <math.h>
#include <stdint.h>

#define NMAX 50000
#define EMAX 1600000

// ---------------- scratch (static device globals; no allocation) ----------------
__device__ float  g_x[NMAX * 128];
__device__ __half g_ft[NMAX * 128];
__device__ float  g_el[NMAX * 8];
__device__ float  g_er[NMAX * 8];
__device__ __half g_p[NMAX * 128];
__device__ __half g_q[NMAX * 128];
__device__ int    g_deg[NMAX];          // zero-init at load; re-zeroed by scatter_csr
__device__ int    g_cur[NMAX];
__device__ int    g_rowstart[NMAX + 1];
__device__ int    g_csrc[EMAX];
__device__ int    g_ceid[EMAX];
__device__ int    g_bsum[256];
__device__ int    g_boff[256];
__device__ uint2  g_wpack[7 * 8 * 16 * 32];   // 7 matrices, fp16 B-fragments

// ---------------- fp16 mma helper ----------------
__device__ __forceinline__ void mma_f16(float& c0, float& c1, float& c2, float& c3,
                                        uint32_t a0, uint32_t a1, uint32_t a2, uint32_t a3,
                                        uint32_t b0, uint32_t b1)
{
    asm volatile("mma.sync.aligned.m16n8k16.row.col.f32.f16.f16.f32 "
                 "{%0,%1,%2,%3}, {%4,%5,%6,%7}, {%8,%9}, {%0,%1,%2,%3};"
                 : "+f"(c0), "+f"(c1), "+f"(c2), "+f"(c3)
                 : "r"(a0), "r"(a1), "r"(a2), "r"(a3), "r"(b0), "r"(b1));
}

// ---------------- pack all 7 W[128,128] into fp16 B fragments (one launch) ----------------
__global__ void pack_w16_all(const float* __restrict__ W_emb, const float* __restrict__ W_g,
                             const float* __restrict__ W_l, const float* __restrict__ W1,
                             uint2* __restrict__ out)
{
    int m = blockIdx.y;
    const float* W;
    if (m == 0)      W = W_emb;
    else if (m < 4)  W = W_g + (size_t)(m - 1) * 128 * 128;
    else if (m == 4) W = W_l;
    else             W = W1 + (size_t)(m - 5) * 128 * 128;

    int i = blockIdx.x * 256 + threadIdx.x;        // 4096 per matrix
    int lane = i & 31, nt = (i >> 5) & 15, kt = i >> 9;
    int tc = lane & 3, gr = lane >> 2;
    int k0 = kt * 16, n = nt * 8 + gr;
    __half2 b0 = __floats2half2_rn(W[(k0 + 2 * tc) * 128 + n],
                                   W[(k0 + 2 * tc + 1) * 128 + n]);
    __half2 b1 = __floats2half2_rn(W[(k0 + 2 * tc + 8) * 128 + n],
                                   W[(k0 + 2 * tc + 9) * 128 + n]);
    uint2 u;
    u.x = *(uint32_t*)&b0;
    u.y = *(uint32_t*)&b1;
    out[(size_t)m * 4096 + i] = u;
}

// ---------------- fp16 GEMM + optional fused attention logits ----------------
template<int H, int OUT, int PQ>
__global__ __launch_bounds__(128)
void gemm_f16(const float* __restrict__ A, const uint2* __restrict__ Bp,
              const float* __restrict__ bias, float* __restrict__ Cf,
              __half2* __restrict__ Ch, __half2* __restrict__ Ch2,
              const float* __restrict__ alp, const float* __restrict__ arp,
              float* __restrict__ el, float* __restrict__ er, int M)
{
    __shared__ __half As[64 * 136];
    __shared__ uint2  Bs[4096];
    int t = threadIdx.x, lane = t & 31, warp = t >> 5;
    int tc = lane & 3, gr = lane >> 2;
    int row0 = blockIdx.x * 64;

    if (PQ) {
        if (blockIdx.y == 1) { Bp += 4096; Ch = Ch2; }
    }

#pragma unroll
    for (int i = 0; i < 32; i++) Bs[t + i * 128] = __ldg(&Bp[t + i * 128]);

    const float4* A4 = (const float4*)A;
#pragma unroll
    for (int i = 0; i < 16; i++) {
        int f = t + i * 128;
        int r = f >> 5, c4 = f & 31;
        int grow = row0 + r;
        float4 v = (grow < M) ? A4[grow * 32 + c4] : make_float4(0.f, 0.f, 0.f, 0.f);
        __half2 h0 = __floats2half2_rn(v.x, v.y);
        __half2 h1 = __floats2half2_rn(v.z, v.w);
        uint2 u;
        u.x = *(uint32_t*)&h0;
        u.y = *(uint32_t*)&h1;
        *(uint2*)&As[r * 136 + c4 * 4] = u;
    }
    __syncthreads();

    float c[16][4];
#pragma unroll
    for (int nt = 0; nt < 16; nt++)
#pragma unroll
        for (int j = 0; j < 4; j++) c[nt][j] = 0.f;

    int m0 = warp * 16;
    const __half* Ar0 = As + (m0 + gr) * 136;
    const __half* Ar1 = Ar0 + 8 * 136;

#pragma unroll
    for (int kt = 0; kt < 8; kt++) {
        int k0 = kt * 16;
        uint32_t a0 = *(const uint32_t*)&Ar0[k0 + 2 * tc];
        uint32_t a1 = *(const uint32_t*)&Ar1[k0 + 2 * tc];
        uint32_t a2 = *(const uint32_t*)&Ar0[k0 + 2 * tc + 8];
        uint32_t a3 = *(const uint32_t*)&Ar1[k0 + 2 * tc + 8];
        const uint2* bk = Bs + kt * 16 * 32 + lane;
#pragma unroll
        for (int nt = 0; nt < 16; nt++) {
            uint2 b = bk[nt * 32];
            mma_f16(c[nt][0], c[nt][1], c[nt][2], c[nt][3],
                    a0, a1, a2, a3, b.x, b.y);
        }
    }

    int r0 = row0 + m0 + gr;
    int r1 = r0 + 8;

    if (H > 0) {
        constexpr int HH = (H > 0) ? H : 1;
        float el0[HH], er0[HH], el1[HH], er1[HH];
#pragma unroll
        for (int hh = 0; hh < HH; hh++) { el0[hh] = er0[hh] = el1[hh] = er1[hh] = 0.f; }
#pragma unroll
        for (int nt = 0; nt < 16; nt++) {
            int col = nt * 8 + tc * 2;
            int hh = (nt * H) >> 4;
            float a0 = __ldg(&alp[col]), a1 = __ldg(&alp[col + 1]);
            float g0 = __ldg(&arp[col]), g1 = __ldg(&arp[col + 1]);
            el0[hh] += c[nt][0] * a0 + c[nt][1] * a1;
            er0[hh] += c[nt][0] * g0 + c[nt][1] * g1;
            el1[hh] += c[nt][2] * a0 + c[nt][3] * a1;
            er1[hh] += c[nt][2] * g0 + c[nt][3] * g1;
        }
#pragma unroll
        for (int hh = 0; hh < HH; hh++) {
            el0[hh] += __shfl_xor_sync(0xffffffffu, el0[hh], 1);
            el0[hh] += __shfl_xor_sync(0xffffffffu, el0[hh], 2);
            er0[hh] += __shfl_xor_sync(0xffffffffu, er0[hh], 1);
            er0[hh] += __shfl_xor_sync(0xffffffffu, er0[hh], 2);
            el1[hh] += __shfl_xor_sync(0xffffffffu, el1[hh], 1);
            el1[hh] += __shfl_xor_sync(0xffffffffu, el1[hh], 2);
            er1[hh] += __shfl_xor_sync(0xffffffffu, er1[hh], 1);
            er1[hh] += __shfl_xor_sync(0xffffffffu, er1[hh], 2);
        }
        if (tc == 0) {
#pragma unroll
            for (int hh = 0; hh < HH; hh++) {
                if (r0 < M) { el[r0 * HH + hh] = el0[hh]; er[r0 * HH + hh] = er0[hh]; }
                if (r1 < M) { el[r1 * HH + hh] = el1[hh]; er[r1 * HH + hh] = er1[hh]; }
            }
        }
    }

#pragma unroll
    for (int nt = 0; nt < 16; nt++) {
        int col = nt * 8 + tc * 2;
        float b0 = 0.f, b1 = 0.f;
        if (bias) { b0 = __ldg(&bias[col]); b1 = __ldg(&bias[col + 1]); }
        float v00 = c[nt][0] + b0, v01 = c[nt][1] + b1;
        float v10 = c[nt][2] + b0, v11 = c[nt][3] + b1;
        if (OUT == 0) {
            if (r0 < M) *(float2*)&Cf[r0 * 128 + col] = make_float2(v00, v01);
            if (r1 < M) *(float2*)&Cf[r1 * 128 + col] = make_float2(v10, v11);
        } else {
            if (r0 < M) Ch[r0 * 64 + nt * 4 + tc] = __floats2half2_rn(v00, v01);
            if (r1 < M) Ch[r1 * 64 + nt * 4 + tc] = __floats2half2_rn(v10, v11);
        }
    }
}

// ---------------- CSR build (parallel) ----------------
__global__ void hist_dst(const int* __restrict__ dst, int* __restrict__ deg, int E)
{
    int base = (blockIdx.x * blockDim.x + threadIdx.x) * 4;
    if (base + 3 < E) {
        int4 d = *(const int4*)(dst + base);
        atomicAdd(&deg[d.x], 1);
        atomicAdd(&deg[d.y], 1);
        atomicAdd(&deg[d.z], 1);
        atomicAdd(&deg[d.w], 1);
    } else {
        for (int e = base; e < E; e++) atomicAdd(&deg[dst[e]], 1);
    }
}

__global__ void scan_p1(const int* __restrict__ deg, int* __restrict__ bsum, int n)
{
    __shared__ int sh[256];
    int i = blockIdx.x * 256 + threadIdx.x;
    int v = (i < n) ? deg[i] : 0;
    sh[threadIdx.x] = v;
    __syncthreads();
#pragma unroll
    for (int off = 128; off > 0; off >>= 1) {
        if (threadIdx.x < off) sh[threadIdx.x] += sh[threadIdx.x + off];
        __syncthreads();
    }
    if (threadIdx.x == 0) bsum[blockIdx.x] = sh[0];
}

__global__ void scan_p2(const int* __restrict__ bsum, int* __restrict__ boff, int nb)
{
    __shared__ int sh[256];
    int t = threadIdx.x;
    int v = (t < nb) ? bsum[t] : 0;
    sh[t] = v;
    __syncthreads();
#pragma unroll
    for (int off = 1; off < 256; off <<= 1) {
        int u = (t >= off) ? sh[t - off] : 0;
        __syncthreads();
        sh[t] += u;
        __syncthreads();
    }
    if (t < nb) boff[t] = sh[t] - v;
}

__global__ void scan_p3(const int* __restrict__ deg, const int* __restrict__ boff,
                        int* __restrict__ rowstart, int* __restrict__ cur, int n, int E)
{
    __shared__ int sh[256];
    int t = threadIdx.x;
    int i = blockIdx.x * 256 + t;
    int v = (i < n) ? deg[i] : 0;
    sh[t] = v;
    __syncthreads();
#pragma unroll
    for (int off = 1; off < 256; off <<= 1) {
        int u = (t >= off) ? sh[t - off] : 0;
        __syncthreads();
        sh[t] += u;
        __syncthreads();
    }
    if (i < n) {
        int r = boff[blockIdx.x] + sh[t] - v;
        rowstart[i] = r;
        cur[i] = r;
    }
    if (i == 0) rowstart[n] = E;
}

// scatter (src + original edge id) + re-zero deg for next replay
__global__ void scatter_csr(const int* __restrict__ src, const int* __restrict__ dst,
                            int* __restrict__ cur, int* __restrict__ csrc,
                            int* __restrict__ ceid, int* __restrict__ deg, int E, int NN)
{
    int tid = blockIdx.x * blockDim.x + threadIdx.x;
    int base = tid * 4;
    if (base + 3 < E) {
        int4 d = *(const int4*)(dst + base);
        int4 s = *(const int4*)(src + base);
        int p0 = atomicAdd(&cur[d.x], 1); csrc[p0] = s.x; ceid[p0] = base;
        int p1 = atomicAdd(&cur[d.y], 1); csrc[p1] = s.y; ceid[p1] = base + 1;
        int p2 = atomicAdd(&cur[d.z], 1); csrc[p2] = s.z; ceid[p2] = base + 2;
        int p3 = atomicAdd(&cur[d.w], 1); csrc[p3] = s.w; ceid[p3] = base + 3;
    } else {
        for (int e = base; e < E; e++) {
            int p0 = atomicAdd(&cur[dst[e]], 1);
            csrc[p0] = src[e];
            ceid[p0] = e;
        }
    }
    // restore deg = 0 (zero-init invariant for next call)
    if (base < NN) {
        if (base + 3 < NN) *(int4*)(deg + base) = make_int4(0, 0, 0, 0);
        else for (int i = base; i < NN; i++) deg[i] = 0;
    }
}

// ---------------- GAT aggregation: half-warp per edge, LDG.128, 4 chains (R10) ----------------
__global__ void gat_aggregate(const int* __restrict__ rowstart, const int* __restrict__ csrc,
                              const __half* __restrict__ ft, const float* __restrict__ el,
                              const float* __restrict__ er, float* __restrict__ x,
                              int H, int logDh, int NN)
{
    int node = (blockIdx.x * blockDim.x + threadIdx.x) >> 5;
    int lane = threadIdx.x & 31;
    if (node >= NN) return;
    int half = lane >> 4, sl = lane & 15;
    int h = (sl * 8) >> logDh;
    float erv = er[node * H + h];
    int beg = rowstart[node], end = rowstart[node + 1];
    int cnt = end - beg;
    int pairend = beg + (cnt & ~1);

    float s = 0.f;
    float acc[8];
#pragma unroll
    for (int j = 0; j < 8; j++) acc[j] = 0.f;
    const uint4* ft4 = (const uint4*)ft;

    int p = beg + half;
    for (; p + 6 < pairend; p += 8) {
        int n0 = __ldg(&csrc[p]);
        int n1 = __ldg(&csrc[p + 2]);
        int n2 = __ldg(&csrc[p + 4]);
        int n3 = __ldg(&csrc[p + 6]);
        float e0 = __ldg(&el[n0 * H + h]) + erv;
        float e1 = __ldg(&el[n1 * H + h]) + erv;
        float e2 = __ldg(&el[n2 * H + h]) + erv;
        float e3 = __ldg(&el[n3 * H + h]) + erv;
        uint4 u0 = __ldg(&ft4[n0 * 16 + sl]);
        uint4 u1 = __ldg(&ft4[n1 * 16 + sl]);
        uint4 u2 = __ldg(&ft4[n2 * 16 + sl]);
        uint4 u3 = __ldg(&ft4[n3 * 16 + sl]);
        e0 = e0 > 0.f ? e0 : 0.2f * e0;
        e1 = e1 > 0.f ? e1 : 0.2f * e1;
        e2 = e2 > 0.f ? e2 : 0.2f * e2;
        e3 = e3 > 0.f ? e3 : 0.2f * e3;
        float w0 = __expf(e0), w1 = __expf(e1), w2 = __expf(e2), w3 = __expf(e3);
        s += (w0 + w1) + (w2 + w3);
        {
            float2 f0 = __half22float2(*(__half2*)&u0.x);
            float2 f1 = __half22float2(*(__half2*)&u0.y);
            float2 f2 = __half22float2(*(__half2*)&u0.z);
            float2 f3 = __half22float2(*(__half2*)&u0.w);
            float2 g0 = __half22float2(*(__half2*)&u1.x);
            float2 g1 = __half22float2(*(__half2*)&u1.y);
            float2 g2 = __half22float2(*(__half2*)&u1.z);
            float2 g3 = __half22float2(*(__half2*)&u1.w);
            acc[0] += f0.x * w0 + g0.x * w1;
            acc[1] += f0.y * w0 + g0.y * w1;
            acc[2] += f1.x * w0 + g1.x * w1;
            acc[3] += f1.y * w0 + g1.y * w1;
            acc[4] += f2.x * w0 + g2.x * w1;
            acc[5] += f2.y * w0 + g2.y * w1;
            acc[6] += f3.x * w0 + g3.x * w1;
            acc[7] += f3.y * w0 + g3.y * w1;
        }
        {
            float2 f0 = __half22float2(*(__half2*)&u2.x);
            float2 f1 = __half22float2(*(__half2*)&u2.y);
            float2 f2 = __half22float2(*(__half2*)&u2.z);
            float2 f3 = __half22float2(*(__half2*)&u2.w);
            float2 g0 = __half22float2(*(__half2*)&u3.x);
            float2 g1 = __half22float2(*(__half2*)&u3.y);
            float2 g2 = __half22float2(*(__half2*)&u3.z);
            float2 g3 = __half22float2(*(__half2*)&u3.w);
            acc[0] += f0.x * w2 + g0.x * w3;
            acc[1] += f0.y * w2 + g0.y * w3;
            acc[2] += f1.x * w2 + g1.x * w3;
            acc[3] += f1.y * w2 + g1.y * w3;
            acc[4] += f2.x * w2 + g2.x * w3;
            acc[5] += f2.y * w2 + g2.y * w3;
            acc[6] += f3.x * w2 + g3.x * w3;
            acc[7] += f3.y * w2 + g3.y * w3;
        }
    }
    for (; p < pairend; p += 2) {
        int n0 = __ldg(&csrc[p]);
        float e0 = __ldg(&el[n0 * H + h]) + erv;
        e0 = e0 > 0.f ? e0 : 0.2f * e0;
        float w0 = __expf(e0);
        uint4 u0 = __ldg(&ft4[n0 * 16 + sl]);
        s += w0;
        float2 f0 = __half22float2(*(__half2*)&u0.x);
        float2 f1 = __half22float2(*(__half2*)&u0.y);
        float2 f2 = __half22float2(*(__half2*)&u0.z);
        float2 f3 = __half22float2(*(__half2*)&u0.w);
        acc[0] += f0.x * w0; acc[1] += f0.y * w0;
        acc[2] += f1.x * w0; acc[3] += f1.y * w0;
        acc[4] += f2.x * w0; acc[5] += f2.y * w0;
        acc[6] += f3.x * w0; acc[7] += f3.y * w0;
    }
    if ((cnt & 1) && half == 0) {
        int n0 = __ldg(&csrc[end - 1]);
        float e0 = __ldg(&el[n0 * H + h]) + erv;
        e0 = e0 > 0.f ? e0 : 0.2f * e0;
        float w0 = __expf(e0);
        uint4 u0 = __ldg(&ft4[n0 * 16 + sl]);
        s += w0;
        float2 f0 = __half22float2(*(__half2*)&u0.x);
        float2 f1 = __half22float2(*(__half2*)&u0.y);
        float2 f2 = __half22float2(*(__half2*)&u0.z);
        float2 f3 = __half22float2(*(__half2*)&u0.w);
        acc[0] += f0.x * w0; acc[1] += f0.y * w0;
        acc[2] += f1.x * w0; acc[3] += f1.y * w0;
        acc[4] += f2.x * w0; acc[5] += f2.y * w0;
        acc[6] += f3.x * w0; acc[7] += f3.y * w0;
    }

    s += __shfl_xor_sync(0xffffffffu, s, 16);
#pragma unroll
    for (int j = 0; j < 8; j++)
        acc[j] += __shfl_xor_sync(0xffffffffu, acc[j], 16);

    float inv = cnt ? 1.0f / s : 0.f;

    int j0 = half * 4;
    float* xp = x + node * 128 + sl * 8 + half * 4;
    float4 xv = *(float4*)xp;
    float v0 = acc[j0] * inv, v1 = acc[j0 + 1] * inv;
    float v2 = acc[j0 + 2] * inv, v3 = acc[j0 + 3] * inv;
    xv.x += v0 > 0.f ? v0 : expm1f(v0);
    xv.y += v1 > 0.f ? v1 : expm1f(v1);
    xv.z += v2 > 0.f ? v2 : expm1f(v2);
    xv.w += v3 > 0.f ? v3 : expm1f(v3);
    *(float4*)xp = xv;
}

// ---------------- fused edge MLP over CSR: warp per node, q hoisted ----------------
__global__ void edge_mlp_csr(const int* __restrict__ rowstart, const int* __restrict__ csrc,
                             const int* __restrict__ ceid,
                             const uint4* __restrict__ p4, const uint4* __restrict__ q4,
                             const float* __restrict__ b1, const float* __restrict__ W2,
                             const float* __restrict__ b2, const float* __restrict__ W3,
                             const float* __restrict__ b3, float* __restrict__ out, int NN)
{
    extern __shared__ __half dsm[];
    uint2* Bfrag = (uint2*)(dsm + 8 * 16 * 136);   // [8 kt][8 nt][32 lane]

    int t = threadIdx.x, lane = t & 31, warp = t >> 5;
    int tc = lane & 3, gr = lane >> 2;
    int half = lane >> 4, sl = lane & 15;
    __half* Y = dsm + warp * 16 * 136;

    // pack W2[128,64] into fp16 fragments (once per block)
    for (int i = t; i < 8 * 8 * 32; i += 256) {
        int ln = i & 31, nt = (i >> 5) & 7, kt = i >> 8;
        int ltc = ln & 3, lgr = ln >> 2;
        int k0 = kt * 16, n = nt * 8 + lgr;
        __half2 h0 = __floats2half2_rn(W2[(k0 + 2 * ltc) * 64 + n],
                                       W2[(k0 + 2 * ltc + 1) * 64 + n]);
        __half2 h1 = __floats2half2_rn(W2[(k0 + 2 * ltc + 8) * 64 + n],
                                       W2[(k0 + 2 * ltc + 9) * 64 + n]);
        uint2 u;
        u.x = *(uint32_t*)&h0;
        u.y = *(uint32_t*)&h1;
        Bfrag[i] = u;
    }

    __half2 b1h[4];
#pragma unroll
    for (int j = 0; j < 4; j++)
        b1h[j] = __floats2half2_rn(b1[sl * 8 + 2 * j], b1[sl * 8 + 2 * j + 1]);
    const __half2 zero2 = __floats2half2_rn(0.f, 0.f);

    float bc0[8], bc1[8];
    float w3r[8][2][2];
#pragma unroll
    for (int nt = 0; nt < 8; nt++) {
        int col = nt * 8 + tc * 2;
        bc0[nt] = b2[col];
        bc1[nt] = b2[col + 1];
        w3r[nt][0][0] = W3[col * 2];       w3r[nt][0][1] = W3[col * 2 + 1];
        w3r[nt][1][0] = W3[(col + 1) * 2]; w3r[nt][1][1] = W3[(col + 1) * 2 + 1];
    }
    float b30 = b3[0], b31 = b3[1];

    __syncthreads();

    int node = blockIdx.x * 8 + warp;
    if (node >= NN) return;
    int beg = rowstart[node], end = rowstart[node + 1];
    if (beg == end) return;

    // q row for this node, held in registers (exact op order preserved below)
    uint4 qv = __ldg(&q4[node * 16 + sl]);

    for (int base = beg; base < end; base += 16) {
        // gather p for up to 16 edges (half-warp per edge)
#pragma unroll
        for (int i = 0; i < 16; i += 2) {
            int pos = base + i + half;
            uint4 yv = make_uint4(0u, 0u, 0u, 0u);
            if (pos < end) {
                int s = __ldg(&csrc[pos]);
                uint4 pv = __ldg(&p4[s * 16 + sl]);
                __half2 y0 = __hmax2(__hadd2(__hadd2(*(__half2*)&pv.x, *(__half2*)&qv.x), b1h[0]), zero2);
                __half2 y1 = __hmax2(__hadd2(__hadd2(*(__half2*)&pv.y, *(__half2*)&qv.y), b1h[1]), zero2);
                __half2 y2 = __hmax2(__hadd2(__hadd2(*(__half2*)&pv.z, *(__half2*)&qv.z), b1h[2]), zero2);
                __half2 y3 = __hmax2(__hadd2(__hadd2(*(__half2*)&pv.w, *(__half2*)&qv.w), b1h[3]), zero2);
                yv.x = *(uint32_t*)&y0;
                yv.y = *(uint32_t*)&y1;
                yv.z = *(uint32_t*)&y2;
                yv.w = *(uint32_t*)&y3;
            }
            *(uint4*)&Y[(i + half) * 136 + sl * 8] = yv;
        }
        __syncwarp();

        float c[8][4];
#pragma unroll
        for (int nt = 0; nt < 8; nt++) {
            c[nt][0] = bc0[nt]; c[nt][1] = bc1[nt];
            c[nt][2] = bc0[nt]; c[nt][3] = bc1[nt];
        }
        const __half* Ar0 = Y + gr * 136;
        const __half* Ar1 = Ar0 + 8 * 136;
#pragma unroll
        for (int kt = 0; kt < 8; kt++) {
            int k0 = kt * 16;
            uint32_t a0 = *(const uint32_t*)&Ar0[k0 + 2 * tc];
            uint32_t a1 = *(const uint32_t*)&Ar1[k0 + 2 * tc];
            uint32_t a2 = *(const uint32_t*)&Ar0[k0 + 2 * tc + 8];
            uint32_t a3 = *(const uint32_t*)&Ar1[k0 + 2 * tc + 8];
            const uint2* bk = Bfrag + kt * 8 * 32 + lane;
#pragma unroll
            for (int nt = 0; nt < 8; nt++) {
                uint2 b = bk[nt * 32];
                mma_f16(c[nt][0], c[nt][1], c[nt][2], c[nt][3],
                        a0, a1, a2, a3, b.x, b.y);
            }
        }

        float pr00 = 0.f, pr01 = 0.f, pr10 = 0.f, pr11 = 0.f;
#pragma unroll
        for (int nt = 0; nt < 8; nt++) {
            float v0 = fmaxf(c[nt][0], 0.f);
            float v1 = fmaxf(c[nt][1], 0.f);
            float v2 = fmaxf(c[nt][2], 0.f);
            float v3 = fmaxf(c[nt][3], 0.f);
            pr00 += v0 * w3r[nt][0][0] + v1 * w3r[nt][1][0];
            pr01 += v0 * w3r[nt][0][1] + v1 * w3r[nt][1][1];
            pr10 += v2 * w3r[nt][0][0] + v3 * w3r[nt][1][0];
            pr11 += v2 * w3r[nt][0][1] + v3 * w3r[nt][1][1];
        }
#pragma unroll
        for (int off = 1; off <= 2; off <<= 1) {
            pr00 += __shfl_xor_sync(0xffffffffu, pr00, off);
            pr01 += __shfl_xor_sync(0xffffffffu, pr01, off);
            pr10 += __shfl_xor_sync(0xffffffffu, pr10, off);
            pr11 += __shfl_xor_sync(0xffffffffu, pr11, off);
        }
        if (tc == 0) {
            int pos0 = base + gr, pos1 = base + gr + 8;
            if (pos0 < end) {
                int e = __ldg(&ceid[pos0]);
                *(float2*)&out[e * 2] = make_float2(pr00 + b30, pr01 + b31);
            }
            if (pos1 < end) {
                int e = __ldg(&ceid[pos1]);
                *(float2*)&out[e * 2] = make_float2(pr10 + b30, pr11 + b31);
            }
        }
        __syncwarp();
    }
}

// ---------------- host launcher ----------------
extern "C" void kernel_launch(void* const* d_in, const int* in_sizes, int n_in,
                              void* d_out, int out_size)
{
    const float* h     = (const float*)d_in[0];
    const int*   src   = (const int*)d_in[1];
    const int*   dst   = (const int*)d_in[2];
    const float* W_emb = (const float*)d_in[3];
    const float* b_emb = (const float*)d_in[4];
    const float* W_g   = (const float*)d_in[5];
    const float* al_g  = (const float*)d_in[6];
    const float* ar_g  = (const float*)d_in[7];
    const float* W_l   = (const float*)d_in[8];
    const float* al_l  = (const float*)d_in[9];
    const float* ar_l  = (const float*)d_in[10];
    const float* W1    = (const float*)d_in[11];
    const float* b1    = (const float*)d_in[12];
    const float* W2    = (const float*)d_in[13];
    const float* b2    = (const float*)d_in[14];
    const float* W3    = (const float*)d_in[15];
    const float* b3    = (const float*)d_in[16];
    float* out = (float*)d_out;

    int NN = in_sizes[0] / 128;
    int NE = in_sizes[1];

    float *x, *el, *er;
    __half *ft, *p, *q;
    int *deg, *cur, *rowstart, *csrc, *ceid, *bsum, *boff;
    uint2* wpack;
    cudaGetSymbolAddress((void**)&x,   g_x);
    cudaGetSymbolAddress((void**)&ft,  g_ft);
    cudaGetSymbolAddress((void**)&el,  g_el);
    cudaGetSymbolAddress((void**)&er,  g_er);
    cudaGetSymbolAddress((void**)&p,   g_p);
    cudaGetSymbolAddress((void**)&q,   g_q);
    cudaGetSymbolAddress((void**)&deg, g_deg);
    cudaGetSymbolAddress((void**)&cur, g_cur);
    cudaGetSymbolAddress((void**)&rowstart, g_rowstart);
    cudaGetSymbolAddress((void**)&csrc, g_csrc);
    cudaGetSymbolAddress((void**)&ceid, g_ceid);
    cudaGetSymbolAddress((void**)&bsum, g_bsum);
    cudaGetSymbolAddress((void**)&boff, g_boff);
    cudaGetSymbolAddress((void**)&wpack, g_wpack);

    const int FR = 8 * 16 * 32;   // uint2 per packed matrix

    pack_w16_all<<<dim3(16, 7), 256>>>(W_emb, W_g, W_l, W1, wpack);

    int snb = (NN + 255) / 256;
    int et4 = (NE + 1023) / 1024;
    hist_dst<<<et4, 256>>>(dst, deg, NE);
    scan_p1<<<snb, 256>>>(deg, bsum, NN);
    scan_p2<<<1, 256>>>(bsum, boff, snb);
    scan_p3<<<snb, 256>>>(deg, boff, rowstart, cur, NN, NE);
    scatter_csr<<<et4, 256>>>(src, dst, cur, csrc, ceid, deg, NE, NN);

    int gemm_blocks = (NN + 63) / 64;

    gemm_f16<0, 0, 0><<<gemm_blocks, 128>>>(h, wpack + 0 * FR, b_emb, x, nullptr, nullptr,
                                            nullptr, nullptr, nullptr, nullptr, NN);

    for (int L = 0; L < 4; L++) {
        const uint2* Wp = wpack + (size_t)(L + 1) * FR;
        if (L < 3) {
            gemm_f16<8, 1, 0><<<gemm_blocks, 128>>>(x, Wp, nullptr, nullptr, (__half2*)ft,
                                                    nullptr, al_g + (size_t)L * 128,
                                                    ar_g + (size_t)L * 128, el, er, NN);
            gat_aggregate<<<(NN * 32 + 255) / 256, 256>>>(rowstart, csrc, ft, el, er, x,
                                                          8, 4, NN);
        } else {
            gemm_f16<1, 1, 0><<<gemm_blocks, 128>>>(x, Wp, nullptr, nullptr, (__half2*)ft,
                                                    nullptr, al_l, ar_l, el, er, NN);
            gat_aggregate<<<(NN * 32 + 255) / 256, 256>>>(rowstart, csrc, ft, el, er, x,
                                                          1, 7, NN);
        }
    }

    gemm_f16<0, 1, 1><<<dim3(gemm_blocks, 2), 128>>>(x, wpack + 5 * FR, nullptr, nullptr,
                                                     (__half2*)p, (__half2*)q,
                                                     nullptr, nullptr, nullptr, nullptr, NN);

    // fused edge MLP over CSR (q hoisted per node)
    int mlp_blocks = (NN + 7) / 8;
    size_t smem = 8 * 16 * 136 * sizeof(__half) + 8 * 8 * 32 * sizeof(uint2);
    cudaFuncSetAttribute(edge_mlp_csr, cudaFuncAttributeMaxDynamicSharedMemorySize,
                         (int)smem);
    edge_mlp_csr<<<mlp_blocks, 256, smem>>>(rowstart, csrc, ceid, (const uint4*)p,
                                            (const uint4*)q, b1, W2, b2, W3, b3, out, NN);
}

// round 14
// speedup vs baseline: 1.2004x; 1.2004x over previous
#include <cuda_runtime.h>
#include <cuda_bf16.h>
#include <cuda_fp16.h>
#include <math.h>
#include <stdint.h>

#define NMAX 50000
#define EMAX 1600000

// ---------------- scratch (static device globals; no allocation) ----------------
__device__ float  g_x[NMAX * 128];
__device__ __half g_ft[NMAX * 128];
__device__ float  g_el[NMAX * 8];
__device__ float  g_er[NMAX * 8];
__device__ __half g_p[NMAX * 128];
__device__ __half g_q[NMAX * 128];
__device__ int    g_deg[NMAX];          // zero-init at load; re-zeroed by scatter_csr
__device__ int    g_cur[NMAX];
__device__ int    g_rowstart[NMAX + 1];
__device__ int    g_csrc[EMAX];
__device__ int    g_bsum[256];
__device__ int    g_boff[256];
__device__ uint2  g_wpack[7 * 8 * 16 * 32];   // 7 matrices, fp16 B-fragments

// ---------------- fp16 mma helper ----------------
__device__ __forceinline__ void mma_f16(float& c0, float& c1, float& c2, float& c3,
                                        uint32_t a0, uint32_t a1, uint32_t a2, uint32_t a3,
                                        uint32_t b0, uint32_t b1)
{
    asm volatile("mma.sync.aligned.m16n8k16.row.col.f32.f16.f16.f32 "
                 "{%0,%1,%2,%3}, {%4,%5,%6,%7}, {%8,%9}, {%0,%1,%2,%3};"
                 : "+f"(c0), "+f"(c1), "+f"(c2), "+f"(c3)
                 : "r"(a0), "r"(a1), "r"(a2), "r"(a3), "r"(b0), "r"(b1));
}

// ---------------- pack all 7 W[128,128] into fp16 B fragments (one launch) ----------------
__global__ void pack_w16_all(const float* __restrict__ W_emb, const float* __restrict__ W_g,
                             const float* __restrict__ W_l, const float* __restrict__ W1,
                             uint2* __restrict__ out)
{
    int m = blockIdx.y;
    const float* W;
    if (m == 0)      W = W_emb;
    else if (m < 4)  W = W_g + (size_t)(m - 1) * 128 * 128;
    else if (m == 4) W = W_l;
    else             W = W1 + (size_t)(m - 5) * 128 * 128;

    int i = blockIdx.x * 256 + threadIdx.x;        // 4096 per matrix
    int lane = i & 31, nt = (i >> 5) & 15, kt = i >> 9;
    int tc = lane & 3, gr = lane >> 2;
    int k0 = kt * 16, n = nt * 8 + gr;
    __half2 b0 = __floats2half2_rn(W[(k0 + 2 * tc) * 128 + n],
                                   W[(k0 + 2 * tc + 1) * 128 + n]);
    __half2 b1 = __floats2half2_rn(W[(k0 + 2 * tc + 8) * 128 + n],
                                   W[(k0 + 2 * tc + 9) * 128 + n]);
    uint2 u;
    u.x = *(uint32_t*)&b0;
    u.y = *(uint32_t*)&b1;
    out[(size_t)m * 4096 + i] = u;
}

// ---------------- fp16 GEMM + optional fused attention logits ----------------
template<int H, int OUT, int PQ>
__global__ __launch_bounds__(128)
void gemm_f16(const float* __restrict__ A, const uint2* __restrict__ Bp,
              const float* __restrict__ bias, float* __restrict__ Cf,
              __half2* __restrict__ Ch, __half2* __restrict__ Ch2,
              const float* __restrict__ alp, const float* __restrict__ arp,
              float* __restrict__ el, float* __restrict__ er, int M)
{
    __shared__ __half As[64 * 136];
    __shared__ uint2  Bs[4096];
    int t = threadIdx.x, lane = t & 31, warp = t >> 5;
    int tc = lane & 3, gr = lane >> 2;
    int row0 = blockIdx.x * 64;

    if (PQ) {
        if (blockIdx.y == 1) { Bp += 4096; Ch = Ch2; }
    }

#pragma unroll
    for (int i = 0; i < 32; i++) Bs[t + i * 128] = __ldg(&Bp[t + i * 128]);

    const float4* A4 = (const float4*)A;
#pragma unroll
    for (int i = 0; i < 16; i++) {
        int f = t + i * 128;
        int r = f >> 5, c4 = f & 31;
        int grow = row0 + r;
        float4 v = (grow < M) ? A4[grow * 32 + c4] : make_float4(0.f, 0.f, 0.f, 0.f);
        __half2 h0 = __floats2half2_rn(v.x, v.y);
        __half2 h1 = __floats2half2_rn(v.z, v.w);
        uint2 u;
        u.x = *(uint32_t*)&h0;
        u.y = *(uint32_t*)&h1;
        *(uint2*)&As[r * 136 + c4 * 4] = u;
    }
    __syncthreads();

    float c[16][4];
#pragma unroll
    for (int nt = 0; nt < 16; nt++)
#pragma unroll
        for (int j = 0; j < 4; j++) c[nt][j] = 0.f;

    int m0 = warp * 16;
    const __half* Ar0 = As + (m0 + gr) * 136;
    const __half* Ar1 = Ar0 + 8 * 136;

#pragma unroll
    for (int kt = 0; kt < 8; kt++) {
        int k0 = kt * 16;
        uint32_t a0 = *(const uint32_t*)&Ar0[k0 + 2 * tc];
        uint32_t a1 = *(const uint32_t*)&Ar1[k0 + 2 * tc];
        uint32_t a2 = *(const uint32_t*)&Ar0[k0 + 2 * tc + 8];
        uint32_t a3 = *(const uint32_t*)&Ar1[k0 + 2 * tc + 8];
        const uint2* bk = Bs + kt * 16 * 32 + lane;
#pragma unroll
        for (int nt = 0; nt < 16; nt++) {
            uint2 b = bk[nt * 32];
            mma_f16(c[nt][0], c[nt][1], c[nt][2], c[nt][3],
                    a0, a1, a2, a3, b.x, b.y);
        }
    }

    int r0 = row0 + m0 + gr;
    int r1 = r0 + 8;

    if (H > 0) {
        constexpr int HH = (H > 0) ? H : 1;
        float el0[HH], er0[HH], el1[HH], er1[HH];
#pragma unroll
        for (int hh = 0; hh < HH; hh++) { el0[hh] = er0[hh] = el1[hh] = er1[hh] = 0.f; }
#pragma unroll
        for (int nt = 0; nt < 16; nt++) {
            int col = nt * 8 + tc * 2;
            int hh = (nt * H) >> 4;
            float a0 = __ldg(&alp[col]), a1 = __ldg(&alp[col + 1]);
            float g0 = __ldg(&arp[col]), g1 = __ldg(&arp[col + 1]);
            el0[hh] += c[nt][0] * a0 + c[nt][1] * a1;
            er0[hh] += c[nt][0] * g0 + c[nt][1] * g1;
            el1[hh] += c[nt][2] * a0 + c[nt][3] * a1;
            er1[hh] += c[nt][2] * g0 + c[nt][3] * g1;
        }
#pragma unroll
        for (int hh = 0; hh < HH; hh++) {
            el0[hh] += __shfl_xor_sync(0xffffffffu, el0[hh], 1);
            el0[hh] += __shfl_xor_sync(0xffffffffu, el0[hh], 2);
            er0[hh] += __shfl_xor_sync(0xffffffffu, er0[hh], 1);
            er0[hh] += __shfl_xor_sync(0xffffffffu, er0[hh], 2);
            el1[hh] += __shfl_xor_sync(0xffffffffu, el1[hh], 1);
            el1[hh] += __shfl_xor_sync(0xffffffffu, el1[hh], 2);
            er1[hh] += __shfl_xor_sync(0xffffffffu, er1[hh], 1);
            er1[hh] += __shfl_xor_sync(0xffffffffu, er1[hh], 2);
        }
        if (tc == 0) {
#pragma unroll
            for (int hh = 0; hh < HH; hh++) {
                if (r0 < M) { el[r0 * HH + hh] = el0[hh]; er[r0 * HH + hh] = er0[hh]; }
                if (r1 < M) { el[r1 * HH + hh] = el1[hh]; er[r1 * HH + hh] = er1[hh]; }
            }
        }
    }

#pragma unroll
    for (int nt = 0; nt < 16; nt++) {
        int col = nt * 8 + tc * 2;
        float b0 = 0.f, b1 = 0.f;
        if (bias) { b0 = __ldg(&bias[col]); b1 = __ldg(&bias[col + 1]); }
        float v00 = c[nt][0] + b0, v01 = c[nt][1] + b1;
        float v10 = c[nt][2] + b0, v11 = c[nt][3] + b1;
        if (OUT == 0) {
            if (r0 < M) *(float2*)&Cf[r0 * 128 + col] = make_float2(v00, v01);
            if (r1 < M) *(float2*)&Cf[r1 * 128 + col] = make_float2(v10, v11);
        } else {
            if (r0 < M) Ch[r0 * 64 + nt * 4 + tc] = __floats2half2_rn(v00, v01);
            if (r1 < M) Ch[r1 * 64 + nt * 4 + tc] = __floats2half2_rn(v10, v11);
        }
    }
}

// ---------------- CSR build (parallel) ----------------
__global__ void hist_dst(const int* __restrict__ dst, int* __restrict__ deg, int E)
{
    int base = (blockIdx.x * blockDim.x + threadIdx.x) * 4;
    if (base + 3 < E) {
        int4 d = *(const int4*)(dst + base);
        atomicAdd(&deg[d.x], 1);
        atomicAdd(&deg[d.y], 1);
        atomicAdd(&deg[d.z], 1);
        atomicAdd(&deg[d.w], 1);
    } else {
        for (int e = base; e < E; e++) atomicAdd(&deg[dst[e]], 1);
    }
}

__global__ void scan_p1(const int* __restrict__ deg, int* __restrict__ bsum, int n)
{
    __shared__ int sh[256];
    int i = blockIdx.x * 256 + threadIdx.x;
    int v = (i < n) ? deg[i] : 0;
    sh[threadIdx.x] = v;
    __syncthreads();
#pragma unroll
    for (int off = 128; off > 0; off >>= 1) {
        if (threadIdx.x < off) sh[threadIdx.x] += sh[threadIdx.x + off];
        __syncthreads();
    }
    if (threadIdx.x == 0) bsum[blockIdx.x] = sh[0];
}

__global__ void scan_p2(const int* __restrict__ bsum, int* __restrict__ boff, int nb)
{
    __shared__ int sh[256];
    int t = threadIdx.x;
    int v = (t < nb) ? bsum[t] : 0;
    sh[t] = v;
    __syncthreads();
#pragma unroll
    for (int off = 1; off < 256; off <<= 1) {
        int u = (t >= off) ? sh[t - off] : 0;
        __syncthreads();
        sh[t] += u;
        __syncthreads();
    }
    if (t < nb) boff[t] = sh[t] - v;
}

__global__ void scan_p3(const int* __restrict__ deg, const int* __restrict__ boff,
                        int* __restrict__ rowstart, int* __restrict__ cur, int n, int E)
{
    __shared__ int sh[256];
    int t = threadIdx.x;
    int i = blockIdx.x * 256 + t;
    int v = (i < n) ? deg[i] : 0;
    sh[t] = v;
    __syncthreads();
#pragma unroll
    for (int off = 1; off < 256; off <<= 1) {
        int u = (t >= off) ? sh[t - off] : 0;
        __syncthreads();
        sh[t] += u;
        __syncthreads();
    }
    if (i < n) {
        int r = boff[blockIdx.x] + sh[t] - v;
        rowstart[i] = r;
        cur[i] = r;
    }
    if (i == 0) rowstart[n] = E;
}

// scatter + re-zero deg for next graph replay (deg is dead after scan_p3)
__global__ void scatter_csr(const int* __restrict__ src, const int* __restrict__ dst,
                            int* __restrict__ cur, int* __restrict__ csrc,
                            int* __restrict__ deg, int E, int NN)
{
    int tid = blockIdx.x * blockDim.x + threadIdx.x;
    int base = tid * 4;
    if (base + 3 < E) {
        int4 d = *(const int4*)(dst + base);
        int4 s = *(const int4*)(src + base);
        csrc[atomicAdd(&cur[d.x], 1)] = s.x;
        csrc[atomicAdd(&cur[d.y], 1)] = s.y;
        csrc[atomicAdd(&cur[d.z], 1)] = s.z;
        csrc[atomicAdd(&cur[d.w], 1)] = s.w;
    } else {
        for (int e = base; e < E; e++)
            csrc[atomicAdd(&cur[dst[e]], 1)] = src[e];
    }
    // restore deg = 0 (zero-init invariant for next call)
    if (base < NN) {
        if (base + 3 < NN) *(int4*)(deg + base) = make_int4(0, 0, 0, 0);
        else for (int i = base; i < NN; i++) deg[i] = 0;
    }
}

// ---------------- GAT aggregation: half-warp per edge, LDG.128, 4 chains (R10) ----------------
__global__ void gat_aggregate(const int* __restrict__ rowstart, const int* __restrict__ csrc,
                              const __half* __restrict__ ft, const float* __restrict__ el,
                              const float* __restrict__ er, float* __restrict__ x,
                              int H, int logDh, int NN)
{
    int node = (blockIdx.x * blockDim.x + threadIdx.x) >> 5;
    int lane = threadIdx.x & 31;
    if (node >= NN) return;
    int half = lane >> 4, sl = lane & 15;
    int h = (sl * 8) >> logDh;
    float erv = er[node * H + h];
    int beg = rowstart[node], end = rowstart[node + 1];
    int cnt = end - beg;
    int pairend = beg + (cnt & ~1);

    float s = 0.f;
    float acc[8];
#pragma unroll
    for (int j = 0; j < 8; j++) acc[j] = 0.f;
    const uint4* ft4 = (const uint4*)ft;

    int p = beg + half;
    for (; p + 6 < pairend; p += 8) {
        int n0 = __ldg(&csrc[p]);
        int n1 = __ldg(&csrc[p + 2]);
        int n2 = __ldg(&csrc[p + 4]);
        int n3 = __ldg(&csrc[p + 6]);
        float e0 = __ldg(&el[n0 * H + h]) + erv;
        float e1 = __ldg(&el[n1 * H + h]) + erv;
        float e2 = __ldg(&el[n2 * H + h]) + erv;
        float e3 = __ldg(&el[n3 * H + h]) + erv;
        uint4 u0 = __ldg(&ft4[n0 * 16 + sl]);
        uint4 u1 = __ldg(&ft4[n1 * 16 + sl]);
        uint4 u2 = __ldg(&ft4[n2 * 16 + sl]);
        uint4 u3 = __ldg(&ft4[n3 * 16 + sl]);
        e0 = e0 > 0.f ? e0 : 0.2f * e0;
        e1 = e1 > 0.f ? e1 : 0.2f * e1;
        e2 = e2 > 0.f ? e2 : 0.2f * e2;
        e3 = e3 > 0.f ? e3 : 0.2f * e3;
        float w0 = __expf(e0), w1 = __expf(e1), w2 = __expf(e2), w3 = __expf(e3);
        s += (w0 + w1) + (w2 + w3);
        {
            float2 f0 = __half22float2(*(__half2*)&u0.x);
            float2 f1 = __half22float2(*(__half2*)&u0.y);
            float2 f2 = __half22float2(*(__half2*)&u0.z);
            float2 f3 = __half22float2(*(__half2*)&u0.w);
            float2 g0 = __half22float2(*(__half2*)&u1.x);
            float2 g1 = __half22float2(*(__half2*)&u1.y);
            float2 g2 = __half22float2(*(__half2*)&u1.z);
            float2 g3 = __half22float2(*(__half2*)&u1.w);
            acc[0] += f0.x * w0 + g0.x * w1;
            acc[1] += f0.y * w0 + g0.y * w1;
            acc[2] += f1.x * w0 + g1.x * w1;
            acc[3] += f1.y * w0 + g1.y * w1;
            acc[4] += f2.x * w0 + g2.x * w1;
            acc[5] += f2.y * w0 + g2.y * w1;
            acc[6] += f3.x * w0 + g3.x * w1;
            acc[7] += f3.y * w0 + g3.y * w1;
        }
        {
            float2 f0 = __half22float2(*(__half2*)&u2.x);
            float2 f1 = __half22float2(*(__half2*)&u2.y);
            float2 f2 = __half22float2(*(__half2*)&u2.z);
            float2 f3 = __half22float2(*(__half2*)&u2.w);
            float2 g0 = __half22float2(*(__half2*)&u3.x);
            float2 g1 = __half22float2(*(__half2*)&u3.y);
            float2 g2 = __half22float2(*(__half2*)&u3.z);
            float2 g3 = __half22float2(*(__half2*)&u3.w);
            acc[0] += f0.x * w2 + g0.x * w3;
            acc[1] += f0.y * w2 + g0.y * w3;
            acc[2] += f1.x * w2 + g1.x * w3;
            acc[3] += f1.y * w2 + g1.y * w3;
            acc[4] += f2.x * w2 + g2.x * w3;
            acc[5] += f2.y * w2 + g2.y * w3;
            acc[6] += f3.x * w2 + g3.x * w3;
            acc[7] += f3.y * w2 + g3.y * w3;
        }
    }
    for (; p < pairend; p += 2) {
        int n0 = __ldg(&csrc[p]);
        float e0 = __ldg(&el[n0 * H + h]) + erv;
        e0 = e0 > 0.f ? e0 : 0.2f * e0;
        float w0 = __expf(e0);
        uint4 u0 = __ldg(&ft4[n0 * 16 + sl]);
        s += w0;
        float2 f0 = __half22float2(*(__half2*)&u0.x);
        float2 f1 = __half22float2(*(__half2*)&u0.y);
        float2 f2 = __half22float2(*(__half2*)&u0.z);
        float2 f3 = __half22float2(*(__half2*)&u0.w);
        acc[0] += f0.x * w0; acc[1] += f0.y * w0;
        acc[2] += f1.x * w0; acc[3] += f1.y * w0;
        acc[4] += f2.x * w0; acc[5] += f2.y * w0;
        acc[6] += f3.x * w0; acc[7] += f3.y * w0;
    }
    if ((cnt & 1) && half == 0) {
        int n0 = __ldg(&csrc[end - 1]);
        float e0 = __ldg(&el[n0 * H + h]) + erv;
        e0 = e0 > 0.f ? e0 : 0.2f * e0;
        float w0 = __expf(e0);
        uint4 u0 = __ldg(&ft4[n0 * 16 + sl]);
        s += w0;
        float2 f0 = __half22float2(*(__half2*)&u0.x);
        float2 f1 = __half22float2(*(__half2*)&u0.y);
        float2 f2 = __half22float2(*(__half2*)&u0.z);
        float2 f3 = __half22float2(*(__half2*)&u0.w);
        acc[0] += f0.x * w0; acc[1] += f0.y * w0;
        acc[2] += f1.x * w0; acc[3] += f1.y * w0;
        acc[4] += f2.x * w0; acc[5] += f2.y * w0;
        acc[6] += f3.x * w0; acc[7] += f3.y * w0;
    }

    s += __shfl_xor_sync(0xffffffffu, s, 16);
#pragma unroll
    for (int j = 0; j < 8; j++)
        acc[j] += __shfl_xor_sync(0xffffffffu, acc[j], 16);

    float inv = cnt ? 1.0f / s : 0.f;

    int j0 = half * 4;
    float* xp = x + node * 128 + sl * 8 + half * 4;
    float4 xv = *(float4*)xp;
    float v0 = acc[j0] * inv, v1 = acc[j0 + 1] * inv;
    float v2 = acc[j0 + 2] * inv, v3 = acc[j0 + 3] * inv;
    xv.x += v0 > 0.f ? v0 : expm1f(v0);
    xv.y += v1 > 0.f ? v1 : expm1f(v1);
    xv.z += v2 > 0.f ? v2 : expm1f(v2);
    xv.w += v3 > 0.f ? v3 : expm1f(v3);
    *(float4*)xp = xv;
}

// ---------------- fused edge MLP: warp-autonomous 16-edge tiles, LDG.128 gather (R12) ----------------
__global__ void edge_mlp_tc(const int* __restrict__ src, const int* __restrict__ dst,
                            const uint4* __restrict__ p4, const uint4* __restrict__ q4,
                            const float* __restrict__ b1, const float* __restrict__ W2,
                            const float* __restrict__ b2, const float* __restrict__ W3,
                            const float* __restrict__ b3, float* __restrict__ out,
                            int E, int ntiles)
{
    extern __shared__ __half dsm[];
    uint2* Bfrag = (uint2*)(dsm + 8 * 16 * 136);   // [8 kt][8 nt][32 lane]

    int t = threadIdx.x, lane = t & 31, warp = t >> 5;
    int tc = lane & 3, gr = lane >> 2;
    int half = lane >> 4, sl = lane & 15;
    __half* Y = dsm + warp * 16 * 136;

    for (int i = t; i < 8 * 8 * 32; i += 256) {
        int ln = i & 31, nt = (i >> 5) & 7, kt = i >> 8;
        int ltc = ln & 3, lgr = ln >> 2;
        int k0 = kt * 16, n = nt * 8 + lgr;
        __half2 h0 = __floats2half2_rn(W2[(k0 + 2 * ltc) * 64 + n],
                                       W2[(k0 + 2 * ltc + 1) * 64 + n]);
        __half2 h1 = __floats2half2_rn(W2[(k0 + 2 * ltc + 8) * 64 + n],
                                       W2[(k0 + 2 * ltc + 9) * 64 + n]);
        uint2 u;
        u.x = *(uint32_t*)&h0;
        u.y = *(uint32_t*)&h1;
        Bfrag[i] = u;
    }

    __half2 b1h[4];
#pragma unroll
    for (int j = 0; j < 4; j++)
        b1h[j] = __floats2half2_rn(b1[sl * 8 + 2 * j], b1[sl * 8 + 2 * j + 1]);
    const __half2 zero2 = __floats2half2_rn(0.f, 0.f);

    float bc0[8], bc1[8];
    float w3r[8][2][2];
#pragma unroll
    for (int nt = 0; nt < 8; nt++) {
        int col = nt * 8 + tc * 2;
        bc0[nt] = b2[col];
        bc1[nt] = b2[col + 1];
        w3r[nt][0][0] = W3[col * 2];       w3r[nt][0][1] = W3[col * 2 + 1];
        w3r[nt][1][0] = W3[(col + 1) * 2]; w3r[nt][1][1] = W3[(col + 1) * 2 + 1];
    }
    float b30 = b3[0], b31 = b3[1];

    __syncthreads();

    int gw = blockIdx.x * 8 + warp;
    for (int g = gw; g < ntiles; g += gridDim.x * 8) {
        int ebase = g * 16;

#pragma unroll
        for (int i = 0; i < 16; i += 2) {
            int eid = ebase + i + half;
            uint4 yv = make_uint4(0u, 0u, 0u, 0u);
            if (eid < E) {
                int s = __ldg(&src[eid]), d = __ldg(&dst[eid]);
                uint4 pv = __ldg(&p4[s * 16 + sl]);
                uint4 qv = __ldg(&q4[d * 16 + sl]);
                __half2 y0 = __hmax2(__hadd2(__hadd2(*(__half2*)&pv.x, *(__half2*)&qv.x), b1h[0]), zero2);
                __half2 y1 = __hmax2(__hadd2(__hadd2(*(__half2*)&pv.y, *(__half2*)&qv.y), b1h[1]), zero2);
                __half2 y2 = __hmax2(__hadd2(__hadd2(*(__half2*)&pv.z, *(__half2*)&qv.z), b1h[2]), zero2);
                __half2 y3 = __hmax2(__hadd2(__hadd2(*(__half2*)&pv.w, *(__half2*)&qv.w), b1h[3]), zero2);
                yv.x = *(uint32_t*)&y0;
                yv.y = *(uint32_t*)&y1;
                yv.z = *(uint32_t*)&y2;
                yv.w = *(uint32_t*)&y3;
            }
            *(uint4*)&Y[(i + half) * 136 + sl * 8] = yv;
        }
        __syncwarp();

        float c[8][4];
#pragma unroll
        for (int nt = 0; nt < 8; nt++) {
            c[nt][0] = bc0[nt]; c[nt][1] = bc1[nt];
            c[nt][2] = bc0[nt]; c[nt][3] = bc1[nt];
        }
        const __half* Ar0 = Y + gr * 136;
        const __half* Ar1 = Ar0 + 8 * 136;
#pragma unroll
        for (int kt = 0; kt < 8; kt++) {
            int k0 = kt * 16;
            uint32_t a0 = *(const uint32_t*)&Ar0[k0 + 2 * tc];
            uint32_t a1 = *(const uint32_t*)&Ar1[k0 + 2 * tc];
            uint32_t a2 = *(const uint32_t*)&Ar0[k0 + 2 * tc + 8];
            uint32_t a3 = *(const uint32_t*)&Ar1[k0 + 2 * tc + 8];
            const uint2* bk = Bfrag + kt * 8 * 32 + lane;
#pragma unroll
            for (int nt = 0; nt < 8; nt++) {
                uint2 b = bk[nt * 32];
                mma_f16(c[nt][0], c[nt][1], c[nt][2], c[nt][3],
                        a0, a1, a2, a3, b.x, b.y);
            }
        }

        float pr00 = 0.f, pr01 = 0.f, pr10 = 0.f, pr11 = 0.f;
#pragma unroll
        for (int nt = 0; nt < 8; nt++) {
            float v0 = fmaxf(c[nt][0], 0.f);
            float v1 = fmaxf(c[nt][1], 0.f);
            float v2 = fmaxf(c[nt][2], 0.f);
            float v3 = fmaxf(c[nt][3], 0.f);
            pr00 += v0 * w3r[nt][0][0] + v1 * w3r[nt][1][0];
            pr01 += v0 * w3r[nt][0][1] + v1 * w3r[nt][1][1];
            pr10 += v2 * w3r[nt][0][0] + v3 * w3r[nt][1][0];
            pr11 += v2 * w3r[nt][0][1] + v3 * w3r[nt][1][1];
        }
#pragma unroll
        for (int off = 1; off <= 2; off <<= 1) {
            pr00 += __shfl_xor_sync(0xffffffffu, pr00, off);
            pr01 += __shfl_xor_sync(0xffffffffu, pr01, off);
            pr10 += __shfl_xor_sync(0xffffffffu, pr10, off);
            pr11 += __shfl_xor_sync(0xffffffffu, pr11, off);
        }
        if (tc == 0) {
            int e0 = ebase + gr, e1 = ebase + gr + 8;
            if (e0 < E) *(float2*)&out[e0 * 2] = make_float2(pr00 + b30, pr01 + b31);
            if (e1 < E) *(float2*)&out[e1 * 2] = make_float2(pr10 + b30, pr11 + b31);
        }
        __syncwarp();
    }
}

// ---------------- host launcher ----------------
extern "C" void kernel_launch(void* const* d_in, const int* in_sizes, int n_in,
                              void* d_out, int out_size)
{
    const float* h     = (const float*)d_in[0];
    const int*   src   = (const int*)d_in[1];
    const int*   dst   = (const int*)d_in[2];
    const float* W_emb = (const float*)d_in[3];
    const float* b_emb = (const float*)d_in[4];
    const float* W_g   = (const float*)d_in[5];
    const float* al_g  = (const float*)d_in[6];
    const float* ar_g  = (const float*)d_in[7];
    const float* W_l   = (const float*)d_in[8];
    const float* al_l  = (const float*)d_in[9];
    const float* ar_l  = (const float*)d_in[10];
    const float* W1    = (const float*)d_in[11];
    const float* b1    = (const float*)d_in[12];
    const float* W2    = (const float*)d_in[13];
    const float* b2    = (const float*)d_in[14];
    const float* W3    = (const float*)d_in[15];
    const float* b3    = (const float*)d_in[16];
    float* out = (float*)d_out;

    int NN = in_sizes[0] / 128;
    int NE = in_sizes[1];

    float *x, *el, *er;
    __half *ft, *p, *q;
    int *deg, *cur, *rowstart, *csrc, *bsum, *boff;
    uint2* wpack;
    cudaGetSymbolAddress((void**)&x,   g_x);
    cudaGetSymbolAddress((void**)&ft,  g_ft);
    cudaGetSymbolAddress((void**)&el,  g_el);
    cudaGetSymbolAddress((void**)&er,  g_er);
    cudaGetSymbolAddress((void**)&p,   g_p);
    cudaGetSymbolAddress((void**)&q,   g_q);
    cudaGetSymbolAddress((void**)&deg, g_deg);
    cudaGetSymbolAddress((void**)&cur, g_cur);
    cudaGetSymbolAddress((void**)&rowstart, g_rowstart);
    cudaGetSymbolAddress((void**)&csrc, g_csrc);
    cudaGetSymbolAddress((void**)&bsum, g_bsum);
    cudaGetSymbolAddress((void**)&boff, g_boff);
    cudaGetSymbolAddress((void**)&wpack, g_wpack);

    const int FR = 8 * 16 * 32;   // uint2 per packed matrix

    pack_w16_all<<<dim3(16, 7), 256>>>(W_emb, W_g, W_l, W1, wpack);

    int snb = (NN + 255) / 256;
    int et4 = (NE + 1023) / 1024;
    hist_dst<<<et4, 256>>>(dst, deg, NE);
    scan_p1<<<snb, 256>>>(deg, bsum, NN);
    scan_p2<<<1, 256>>>(bsum, boff, snb);
    scan_p3<<<snb, 256>>>(deg, boff, rowstart, cur, NN, NE);
    scatter_csr<<<et4, 256>>>(src, dst, cur, csrc, deg, NE, NN);

    int gemm_blocks = (NN + 63) / 64;

    gemm_f16<0, 0, 0><<<gemm_blocks, 128>>>(h, wpack + 0 * FR, b_emb, x, nullptr, nullptr,
                                            nullptr, nullptr, nullptr, nullptr, NN);

    for (int L = 0; L < 4; L++) {
        const uint2* Wp = wpack + (size_t)(L + 1) * FR;
        if (L < 3) {
            gemm_f16<8, 1, 0><<<gemm_blocks, 128>>>(x, Wp, nullptr, nullptr, (__half2*)ft,
                                                    nullptr, al_g + (size_t)L * 128,
                                                    ar_g + (size_t)L * 128, el, er, NN);
            gat_aggregate<<<(NN * 32 + 255) / 256, 256>>>(rowstart, csrc, ft, el, er, x,
                                                          8, 4, NN);
        } else {
            gemm_f16<1, 1, 0><<<gemm_blocks, 128>>>(x, Wp, nullptr, nullptr, (__half2*)ft,
                                                    nullptr, al_l, ar_l, el, er, NN);
            gat_aggregate<<<(NN * 32 + 255) / 256, 256>>>(rowstart, csrc, ft, el, er, x,
                                                          1, 7, NN);
        }
    }

    gemm_f16<0, 1, 1><<<dim3(gemm_blocks, 2), 128>>>(x, wpack + 5 * FR, nullptr, nullptr,
                                                     (__half2*)p, (__half2*)q,
                                                     nullptr, nullptr, nullptr, nullptr, NN);

    // fused edge MLP: grid sized to exact resident capacity (no partial last wave)
    int ntiles = (NE + 15) / 16;
    size_t smem = 8 * 16 * 136 * sizeof(__half) + 8 * 8 * 32 * sizeof(uint2);
    cudaFuncSetAttribute(edge_mlp_tc, cudaFuncAttributeMaxDynamicSharedMemorySize,
                         (int)smem);
    int nsm = 148, bps = 0;
    cudaDeviceGetAttribute(&nsm, cudaDevAttrMultiProcessorCount, 0);
    cudaOccupancyMaxActiveBlocksPerMultiprocessor(&bps, edge_mlp_tc, 256, smem);
    int mlp_grid = (bps > 0) ? bps * nsm : 1184;
    int max_grid = (ntiles + 7) / 8;
    if (mlp_grid > max_grid) mlp_grid = max_grid;
    edge_mlp_tc<<<mlp_grid, 256, smem>>>(src, dst, (const uint4*)p, (const uint4*)q,
                                         b1, W2, b2, W3, b3, out, NE, ntiles);
}